// round 1
// baseline (speedup 1.0000x reference)
#include <cuda_runtime.h>
#include <math.h>

// Problem constants (fixed shapes from the reference setup)
constexpr int Bn = 4;      // batch
constexpr int Cn = 128;    // fused out channels (64 branch a + 64 branch b) == Cin
constexpr int Hn = 256;
constexpr int Wn = 256;

// Attention map scratch (2 branches x B x H x W), 2 MB — __device__ global (no alloc)
static __device__ float g_att[2][(size_t)Bn * Hn * Wn];

__device__ __forceinline__ unsigned long long pack2f(float v) {
    unsigned long long r;
    unsigned u = __float_as_uint(v);
    asm("mov.b64 %0, {%1, %2};" : "=l"(r) : "r"(u), "r"(u));
    return r;
}
__device__ __forceinline__ void fma2(unsigned long long& d, unsigned long long a,
                                     unsigned long long b) {
    // packed f32x2 FMA — sm_103a FFMA2, 2x fp32 throughput vs scalar FFMA
    asm("fma.rn.f32x2 %0, %1, %2, %3;" : "=l"(d) : "l"(a), "l"(b), "l"(d));
}

// ---------------------------------------------------------------------------
// Pass 1: fused conv3x3(128->128) + bias + branch BN (eps 1e-3)
//         + 1x1 attention conv over [f(64ch), gh, gw] + attention BN (eps 1e-5)
// Writes unscaled f to out[B,128,H,W]; writes att maps to g_att.
// Tile: 64(W) x 4(H) pixels, all 128 oc.
// Thread: 8 px (consecutive W) x 16 oc (one warp = one oc group).
// ---------------------------------------------------------------------------
__global__ __launch_bounds__(256, 1)
void pass1_conv_bn_att(
    const float* __restrict__ x,
    const float* __restrict__ wa, const float* __restrict__ ba,
    const float* __restrict__ wb, const float* __restrict__ bb,
    const float* __restrict__ bnag, const float* __restrict__ bnabt,
    const float* __restrict__ bnam, const float* __restrict__ bnav,
    const float* __restrict__ bnbg, const float* __restrict__ bnbbt,
    const float* __restrict__ bnbm, const float* __restrict__ bnbv,
    const float* __restrict__ attaw, const float* __restrict__ attab,
    const float* __restrict__ attbw, const float* __restrict__ attbbias,
    const float* __restrict__ abnag, const float* __restrict__ abnabt,
    const float* __restrict__ abnam, const float* __restrict__ abnav,
    const float* __restrict__ abnbg, const float* __restrict__ abnbbt,
    const float* __restrict__ abnbm, const float* __restrict__ abnbv,
    float* __restrict__ out)
{
    constexpr int TW = 64, TH = 4, ICC = 4;
    __shared__ union SM {
        struct {
            float xs[ICC][TH + 2][TW + 2];  // [4][6][66]  (66 mod 32 = 2 -> conflict-free)
            float ws[ICC][9][Cn];           // [4][9][128]
        } m;
        float attp[8][TW * TH];             // reused after mainloop (union aliasing)
    } sm;

    const int tid  = threadIdx.x;
    const int ocg  = tid >> 5;          // warp id = oc group (16 oc each)
    const int slot = tid & 31;
    const int srow = slot >> 3;         // 0..3   (H within tile)
    const int scol = (slot & 7) << 3;   // 0..56  (W within tile, x8)
    const int gx0 = blockIdx.x * TW;
    const int gy0 = blockIdx.y * TH;
    const int bz  = blockIdx.z;

    unsigned long long acc[8][8];       // [px][oc pair] = 8 px x 16 oc fp32
    #pragma unroll
    for (int i = 0; i < 8; i++)
        #pragma unroll
        for (int j = 0; j < 8; j++) acc[i][j] = 0ull;

    const float* xb = x + (size_t)bz * Cn * Hn * Wn;

    #pragma unroll 1
    for (int icc = 0; icc < Cn; icc += ICC) {
        // ---- stage x tile (with halo + zero pad) ----
        for (int idx = tid; idx < ICC * 6 * 66; idx += 256) {
            int icl = idx / (6 * 66);
            int rem = idx - icl * (6 * 66);
            int r   = rem / 66;
            int cc2 = rem - r * 66;
            int gr = gy0 - 1 + r;
            int gc = gx0 - 1 + cc2;
            float v = 0.f;
            if ((unsigned)gr < (unsigned)Hn && (unsigned)gc < (unsigned)Wn)
                v = xb[((size_t)(icc + icl) * Hn + gr) * Wn + gc];
            sm.m.xs[icl][r][cc2] = v;
        }
        // ---- stage fused weights [ic][tap][oc] ----
        for (int idx = tid; idx < ICC * 9 * Cn; idx += 256) {
            int oc  = idx & (Cn - 1);
            int rem = idx >> 7;
            int tap = rem % 9;
            int icl = rem / 9;
            const float* wsrc = (oc < 64) ? wa : wb;
            sm.m.ws[icl][tap][oc] = wsrc[((size_t)(oc & 63) * Cn + icc + icl) * 9 + tap];
        }
        __syncthreads();

        // ---- mainloop: FFMA2-bound ----
        #pragma unroll 1
        for (int icl = 0; icl < ICC; icl++) {
            #pragma unroll
            for (int kh = 0; kh < 3; kh++) {
                float xrow[10];
                const float* xr = &sm.m.xs[icl][srow + kh][scol];
                #pragma unroll
                for (int i = 0; i < 10; i++) xrow[i] = xr[i];
                #pragma unroll
                for (int kw = 0; kw < 3; kw++) {
                    // 16 weights for this oc group = 8 packed pairs (warp-uniform LDS)
                    const unsigned long long* wp =
                        (const unsigned long long*)&sm.m.ws[icl][kh * 3 + kw][ocg * 16];
                    unsigned long long wv[8];
                    #pragma unroll
                    for (int j = 0; j < 8; j++) wv[j] = wp[j];
                    #pragma unroll
                    for (int i = 0; i < 8; i++) {
                        unsigned long long xp = pack2f(xrow[i + kw]);
                        #pragma unroll
                        for (int j = 0; j < 8; j++) fma2(acc[i][j], xp, wv[j]);
                    }
                }
            }
        }
        __syncthreads();
    }

    // ---- epilogue: bias + branch BN, store f, accumulate 1x1 attention partials ----
    float ap[8];
    #pragma unroll
    for (int i = 0; i < 8; i++) ap[i] = 0.f;

    const int hrow = gy0 + srow;
    #pragma unroll
    for (int k = 0; k < 16; k++) {
        int oc = ocg * 16 + k;
        bool isB = oc >= 64;
        int ol = oc & 63;
        float gmm = isB ? bnbg[ol]  : bnag[ol];
        float bet = isB ? bnbbt[ol] : bnabt[ol];
        float mu  = isB ? bnbm[ol]  : bnam[ol];
        float var = isB ? bnbv[ol]  : bnav[ol];
        float cb  = isB ? bb[ol]    : ba[ol];
        float aw  = isB ? attbw[ol] : attaw[ol];
        float sc = gmm * rsqrtf(var + 1e-3f);           // branch BN eps
        float sh = (cb - mu) * sc + bet;
        float f[8];
        #pragma unroll
        for (int i = 0; i < 8; i++) {
            unsigned long long p = acc[i][k >> 1];
            float raw = (k & 1) ? __uint_as_float((unsigned)(p >> 32))
                                : __uint_as_float((unsigned)(p & 0xffffffffu));
            f[i] = raw * sc + sh;
            ap[i] += aw * f[i];
        }
        float* op = out + (((size_t)bz * Cn + oc) * Hn + hrow) * Wn + gx0 + scol;
        *(float4*)op       = make_float4(f[0], f[1], f[2], f[3]);
        *(float4*)(op + 4) = make_float4(f[4], f[5], f[6], f[7]);
    }

    // block reduce attention partials across the 8 oc-group warps
    #pragma unroll
    for (int i = 0; i < 8; i++)
        sm.attp[ocg][srow * TW + scol + i] = ap[i];
    __syncthreads();

    {
        int p  = tid;                 // 256 threads <-> 256 tile pixels
        int r  = p >> 6;
        int c2 = p & 63;
        int h = gy0 + r, w = gx0 + c2;
        // position info (H,W even): gh = |i - H/2 + 0.5| / (H/2)
        float ghv = fabsf((float)h - 128.f + 0.5f) * (1.f / 128.f);
        float gwv = fabsf((float)w - 128.f + 0.5f) * (1.f / 128.f);
        float raA = sm.attp[0][p] + sm.attp[1][p] + sm.attp[2][p] + sm.attp[3][p]
                  + attab[0]    + attaw[64] * ghv + attaw[65] * gwv;
        float raB = sm.attp[4][p] + sm.attp[5][p] + sm.attp[6][p] + sm.attp[7][p]
                  + attbbias[0] + attbw[64] * ghv + attbw[65] * gwv;
        float aa = (raA - abnam[0]) * (abnag[0] * rsqrtf(abnav[0] + 1e-5f)) + abnabt[0];
        float ab = (raB - abnbm[0]) * (abnbg[0] * rsqrtf(abnbv[0] + 1e-5f)) + abnbbt[0];
        size_t pi = ((size_t)bz * Hn + h) * Wn + w;
        g_att[0][pi] = aa;
        g_att[1][pi] = ab;
    }
}

// ---------------------------------------------------------------------------
// Pass 2: 3x3 attention conv over [att, gh, gw, pr] + sigmoid, then in-place
// scale of all 128 channels of out. Each thread: 4 consecutive W pixels.
// ---------------------------------------------------------------------------
__global__ __launch_bounds__(256)
void pass2_attn_scale(
    const float* __restrict__ wA, const float* __restrict__ wB,
    const float* __restrict__ s1p, const float* __restrict__ s2p,
    float* __restrict__ out)
{
    int t = blockIdx.x * 256 + threadIdx.x;   // B*H*W/4 = 65536 tasks
    int b   = t >> 14;
    int rem = t & 16383;
    int h   = rem >> 6;
    int w4  = (rem & 63) << 2;

    // polar-r linear remap constants (exact fp32 match of reference min/max)
    const float ghmax = 127.5f / 128.f;
    const float ghmin = 0.5f / 128.f;
    float prmax = sqrtf(ghmax * ghmax + ghmax * ghmax);
    float prmin = sqrtf(ghmin * ghmin + ghmin * ghmin);
    float kk = 2.f / (prmax - prmin);
    float c0 = 1.f - prmax * kk;

    const float* attA = g_att[0] + (size_t)b * Hn * Wn;
    const float* attB = g_att[1] + (size_t)b * Hn * Wn;

    float sA[4] = {0.f, 0.f, 0.f, 0.f};
    float sB[4] = {0.f, 0.f, 0.f, 0.f};
    #pragma unroll
    for (int kh = 0; kh < 3; kh++) {
        int ih = h + kh - 1;
        if ((unsigned)ih >= (unsigned)Hn) continue;     // zero padding: skip all channels
        float ghv = fabsf((float)ih - 128.f + 0.5f) * (1.f / 128.f);
        #pragma unroll
        for (int kw = 0; kw < 3; kw++) {
            int ti = kh * 3 + kw;
            float wa0 = wA[ti], wa1 = wA[9 + ti], wa2 = wA[18 + ti], wa3 = wA[27 + ti];
            float wb0 = wB[ti], wb1 = wB[9 + ti], wb2 = wB[18 + ti], wb3 = wB[27 + ti];
            #pragma unroll
            for (int i = 0; i < 4; i++) {
                int jw = w4 + i + kw - 1;
                if ((unsigned)jw >= (unsigned)Wn) continue;
                float gwv = fabsf((float)jw - 128.f + 0.5f) * (1.f / 128.f);
                float pr = kk * sqrtf(ghv * ghv + gwv * gwv) + c0;
                float av = attA[(size_t)ih * Wn + jw];
                float bv = attB[(size_t)ih * Wn + jw];
                sA[i] += wa0 * av + wa1 * ghv + wa2 * gwv + wa3 * pr;
                sB[i] += wb0 * bv + wb1 * ghv + wb2 * gwv + wb3 * pr;
            }
        }
    }
    float s1 = s1p[0], s2 = s2p[0];
    float ma[4], mb2[4];
    #pragma unroll
    for (int i = 0; i < 4; i++) {
        ma[i]  = s1 / (1.f + expf(-sA[i]));
        mb2[i] = s2 / (1.f + expf(-sB[i]));
    }
    float* base = out + (((size_t)b * Cn) * Hn + h) * Wn + w4;
    #pragma unroll 1
    for (int c = 0; c < Cn; c++) {
        float4* p = (float4*)(base + (size_t)c * Hn * Wn);
        float4 v = *p;
        const float* m = (c < 64) ? ma : mb2;
        v.x *= m[0]; v.y *= m[1]; v.z *= m[2]; v.w *= m[3];
        *p = v;
    }
}

extern "C" void kernel_launch(void* const* d_in, const int* in_sizes, int n_in,
                              void* d_out, int out_size) {
    (void)in_sizes; (void)n_in; (void)out_size;
    const float* P[29];
    for (int i = 0; i < 29; i++) P[i] = (const float*)d_in[i];
    float* out = (float*)d_out;

    dim3 g1(Wn / 64, Hn / 4, Bn);   // 4 x 64 x 4 = 1024 blocks
    pass1_conv_bn_att<<<g1, 256>>>(
        P[0],                        // x
        P[1], P[2], P[3], P[4],      // conv a w/b, conv b w/b
        P[5], P[6], P[7], P[8],      // bn a
        P[9], P[10], P[11], P[12],   // bn b
        P[13], P[14], P[15], P[16],  // att 1x1 w/b a, b
        P[17], P[18], P[19], P[20],  // att bn a
        P[21], P[22], P[23], P[24],  // att bn b
        out);
    pass2_attn_scale<<<(Bn * Hn * Wn / 4) / 256, 256>>>(P[25], P[26], P[27], P[28], out);
}

// round 4
// speedup vs baseline: 3.0957x; 3.0957x over previous
#include <cuda_runtime.h>
#include <cuda_bf16.h>
#include <cstdint>
#include <math.h>

constexpr int Bn = 4, Cn = 128, Hn = 256, Wn = 256;

// ---- device scratch (declared statically; no runtime allocs) ----
static __device__ float g_att[2][(size_t)Bn * Hn * Wn];                              // 2 MB
static __device__ __align__(16) unsigned char g_xnhwc[(size_t)Bn * Hn * Wn * 512];   // 128 MB [b][h][w][hi128|lo128] bf16
static __device__ __align__(16) unsigned char g_w[(size_t)9 * 2 * 128 * 128 * 2];    // 576 KB [tap][hi/lo][oc][ic] bf16

__device__ __forceinline__ unsigned short bf16_bits(__nv_bfloat16 h) {
    return *reinterpret_cast<unsigned short*>(&h);
}
__device__ __forceinline__ uint32_t smem_u32(const void* p) {
    uint32_t a;
    asm("{ .reg .u64 t; cvta.to.shared.u64 t, %1; cvt.u32.u64 %0, t; }" : "=r"(a) : "l"(p));
    return a;
}
__device__ __forceinline__ void ldsm_x4(uint32_t* r, uint32_t addr) {
    asm volatile("ldmatrix.sync.aligned.m8n8.x4.shared.b16 {%0,%1,%2,%3}, [%4];"
                 : "=r"(r[0]), "=r"(r[1]), "=r"(r[2]), "=r"(r[3]) : "r"(addr));
}
__device__ __forceinline__ void mma16816(float* d, const uint32_t* a, const uint32_t* b) {
    asm volatile(
        "mma.sync.aligned.m16n8k16.row.col.f32.bf16.bf16.f32 "
        "{%0,%1,%2,%3}, {%4,%5,%6,%7}, {%8,%9}, {%0,%1,%2,%3};"
        : "+f"(d[0]), "+f"(d[1]), "+f"(d[2]), "+f"(d[3])
        : "r"(a[0]), "r"(a[1]), "r"(a[2]), "r"(a[3]), "r"(b[0]), "r"(b[1]));
}

// ---------------------------------------------------------------------------
// Setup 1: x NCHW fp32 -> NHWC bf16 hi/lo  [b][h][w][hi 128 | lo 128]
// ---------------------------------------------------------------------------
__global__ __launch_bounds__(256)
void xprep(const float* __restrict__ x) {
    __shared__ float tile[128][33];
    int wt = blockIdx.x, hh = blockIdx.y, b = blockIdx.z;
    int t = threadIdx.x, warp = t >> 5, lane = t & 31;
    const float* src = x + (((size_t)b * Cn + warp * 16) * Hn + hh) * Wn + wt * 32 + lane;
    #pragma unroll
    for (int k = 0; k < 16; k++) tile[warp * 16 + k][lane] = src[(size_t)k * Hn * Wn];
    __syncthreads();
    int px = t >> 3, seg = t & 7, icb = seg * 16;
    unsigned int hiv[8], lov[8];
    #pragma unroll
    for (int j = 0; j < 16; j += 2) {
        float v0 = tile[icb + j][px], v1 = tile[icb + j + 1][px];
        __nv_bfloat16 h0 = __float2bfloat16(v0), h1 = __float2bfloat16(v1);
        __nv_bfloat16 l0 = __float2bfloat16(v0 - __bfloat162float(h0));
        __nv_bfloat16 l1 = __float2bfloat16(v1 - __bfloat162float(h1));
        hiv[j >> 1] = (unsigned)bf16_bits(h0) | ((unsigned)bf16_bits(h1) << 16);
        lov[j >> 1] = (unsigned)bf16_bits(l0) | ((unsigned)bf16_bits(l1) << 16);
    }
    size_t p = ((size_t)b * Hn + hh) * Wn + wt * 32 + px;
    unsigned char* dst = g_xnhwc + p * 512;
    *(uint4*)(dst + icb * 2)            = make_uint4(hiv[0], hiv[1], hiv[2], hiv[3]);
    *(uint4*)(dst + icb * 2 + 16)       = make_uint4(hiv[4], hiv[5], hiv[6], hiv[7]);
    *(uint4*)(dst + 256 + icb * 2)      = make_uint4(lov[0], lov[1], lov[2], lov[3]);
    *(uint4*)(dst + 256 + icb * 2 + 16) = make_uint4(lov[4], lov[5], lov[6], lov[7]);
}

// ---------------------------------------------------------------------------
// Setup 2: weights -> g_w[tap][part][oc][ic] bf16 (hi part 0, lo part 1)
// ---------------------------------------------------------------------------
__global__ __launch_bounds__(256)
void wprep(const float* __restrict__ wa, const float* __restrict__ wb) {
    int id = blockIdx.x * 256 + threadIdx.x;
    if (id >= 9 * 128 * 128) return;
    int tap = id / 16384, rem = id & 16383, oc = rem >> 7, ic = rem & 127;
    float w = (oc < 64) ? wa[((size_t)oc * 128 + ic) * 9 + tap]
                        : wb[((size_t)(oc - 64) * 128 + ic) * 9 + tap];
    __nv_bfloat16 hi = __float2bfloat16(w);
    __nv_bfloat16 lo = __float2bfloat16(w - __bfloat162float(hi));
    unsigned char* b0 = g_w + (((size_t)tap * 2 + 0) * 128 + oc) * 256 + ic * 2;
    unsigned char* b1 = g_w + (((size_t)tap * 2 + 1) * 128 + oc) * 256 + ic * 2;
    *(unsigned short*)b0 = bf16_bits(hi);
    *(unsigned short*)b1 = bf16_bits(lo);
}

// ---------------------------------------------------------------------------
// Pass 1: mma.sync bf16 hi/lo implicit-GEMM conv + BN + 1x1 attention reduce.
// CTA = 128 oc x 128 px (half an output row). 8 warps: 2(oc) x 4(px).
// ---------------------------------------------------------------------------
constexpr int SM_WH  = 0;            // 128 x 256B = 32768
constexpr int SM_WL  = 32768;        // 32768
constexpr int SM_XH  = 65536;        // 130 x 256B = 33280
constexpr int SM_XL  = 98816;        // 33280
constexpr int SM_LUT = 132096;       // sc/sh/aw: 3 x 128 f32 = 1536
constexpr int SM_ATT = 133632;       // 2 x 128 f32 = 1024
constexpr int SMEM_BYTES = 134656;

__global__ __launch_bounds__(256)
void pass1_mma(
    const float* __restrict__ ba, const float* __restrict__ bb,
    const float* __restrict__ bnag, const float* __restrict__ bnabt,
    const float* __restrict__ bnam, const float* __restrict__ bnav,
    const float* __restrict__ bnbg, const float* __restrict__ bnbbt,
    const float* __restrict__ bnbm, const float* __restrict__ bnbv,
    const float* __restrict__ attaw, const float* __restrict__ attab,
    const float* __restrict__ attbw, const float* __restrict__ attbbias,
    const float* __restrict__ abnag, const float* __restrict__ abnabt,
    const float* __restrict__ abnam, const float* __restrict__ abnav,
    const float* __restrict__ abnbg, const float* __restrict__ abnbbt,
    const float* __restrict__ abnbm, const float* __restrict__ abnbv,
    float* __restrict__ out)
{
    extern __shared__ char sb[];
    const uint32_t sb32 = smem_u32(sb);

    const int tid = threadIdx.x, wid = tid >> 5, lane = tid & 31;
    const int warpM = wid & 1, warpN = wid >> 1;
    const int px0 = (blockIdx.x & 1) * 128;
    const int h = blockIdx.y, b = blockIdx.z;
    const int ocb = warpM * 64, pxb = warpN * 32;

    // per-oc BN/attention LUTs
    if (tid < 128) {
        int oc = tid; bool isB = oc >= 64; int ol = oc & 63;
        float g  = isB ? bnbg[ol]  : bnag[ol];
        float bt = isB ? bnbbt[ol] : bnabt[ol];
        float mu = isB ? bnbm[ol]  : bnam[ol];
        float vr = isB ? bnbv[ol]  : bnav[ol];
        float cb = isB ? bb[ol]    : ba[ol];
        float sc = g * rsqrtf(vr + 1e-3f);
        float* lut = (float*)(sb + SM_LUT);
        lut[oc]       = sc;
        lut[128 + oc] = (cb - mu) * sc + bt;
        lut[256 + oc] = isB ? attbw[ol] : attaw[ol];
    }

    float acc[4][4][4];
    #pragma unroll
    for (int i = 0; i < 4; i++)
        #pragma unroll
        for (int j = 0; j < 4; j++)
            #pragma unroll
            for (int k = 0; k < 4; k++) acc[i][j][k] = 0.f;

    for (int kh = 0; kh < 3; kh++) {
        const int ih = h + kh - 1;
        if ((unsigned)ih >= (unsigned)Hn) continue;
        __syncthreads();  // previous tap's compute done before overwriting X
        // stage X rows [px0-1 .. px0+128] hi+lo, swizzled
        {
            const unsigned char* xrow = g_xnhwc + ((size_t)b * Hn + ih) * Wn * 512;
            for (int idx = tid; idx < 130 * 16; idx += 256) {
                int r = idx >> 4, c = idx & 15;
                int g = px0 - 1 + r;
                uint4 vh = make_uint4(0u, 0u, 0u, 0u), vl = vh;
                if ((unsigned)g < (unsigned)Wn) {
                    vh = *(const uint4*)(xrow + (size_t)g * 512 + c * 16);
                    vl = *(const uint4*)(xrow + (size_t)g * 512 + 256 + c * 16);
                }
                uint32_t off = (uint32_t)(r * 256 + ((c ^ (r & 7)) << 4));
                *(uint4*)(sb + SM_XH + off) = vh;
                *(uint4*)(sb + SM_XL + off) = vl;
            }
        }
        for (int kw = 0; kw < 3; kw++) {
            const int tap = kh * 3 + kw;
            __syncthreads();  // previous compute done + X visible
            // stage W (hi+lo), swizzled
            {
                const unsigned char* wsrc = g_w + (size_t)tap * 65536;
                for (int idx = tid; idx < 128 * 16; idx += 256) {
                    int r = idx >> 4, c = idx & 15;
                    uint32_t off = (uint32_t)(r * 256 + ((c ^ (r & 7)) << 4));
                    *(uint4*)(sb + SM_WH + off) = *(const uint4*)(wsrc + r * 256 + c * 16);
                    *(uint4*)(sb + SM_WL + off) = *(const uint4*)(wsrc + 32768 + r * 256 + c * 16);
                }
            }
            __syncthreads();  // W visible

            #pragma unroll 1
            for (int kc = 0; kc < 8; kc++) {
                const int cA = kc * 2;  // 16B-chunk base of this k16 slice
                uint32_t ah[4][4], alw[4][4];
                #pragma unroll
                for (int mt = 0; mt < 4; mt++) {
                    int mrow = ocb + mt * 16 + (lane & 15);
                    int cc = cA + (lane >> 4);
                    uint32_t off = (uint32_t)(mrow * 256 + ((cc ^ (mrow & 7)) << 4));
                    ldsm_x4(ah[mt],  sb32 + SM_WH + off);
                    ldsm_x4(alw[mt], sb32 + SM_WL + off);
                }
                // B fragments: X smem is n-major (row = pixel, contiguous ic/k),
                // so NON-trans ldmatrix directly yields the .col B fragment.
                uint32_t bh[2][4], bl[2][4];
                #pragma unroll
                for (int ntp = 0; ntp < 2; ntp++) {
                    int prow = pxb + ntp * 16 + (lane & 7) + ((lane & 16) ? 8 : 0) + kw;
                    int cc = cA + ((lane >> 3) & 1);
                    uint32_t off = (uint32_t)(prow * 256 + ((cc ^ (prow & 7)) << 4));
                    ldsm_x4(bh[ntp], sb32 + SM_XH + off);
                    ldsm_x4(bl[ntp], sb32 + SM_XL + off);
                }
                #pragma unroll
                for (int mt = 0; mt < 4; mt++)
                    #pragma unroll
                    for (int nt = 0; nt < 4; nt++) {
                        float* d = acc[mt][nt];
                        const uint32_t* pbh = &bh[nt >> 1][(nt & 1) * 2];
                        const uint32_t* pbl = &bl[nt >> 1][(nt & 1) * 2];
                        mma16816(d, ah[mt],  pbh);   // xh * wh
                        mma16816(d, alw[mt], pbh);   // xh * wl
                        mma16816(d, ah[mt],  pbl);   // xl * wh
                    }
            }
        }
    }

    // ---- epilogue: BN + store f + 1x1 attention partial ----
    const float* scl = (const float*)(sb + SM_LUT);
    const float* shl = scl + 128;
    const float* awl = scl + 256;
    float* attbuf = (float*)(sb + SM_ATT);

    #pragma unroll
    for (int nt = 0; nt < 4; nt++) {
        float s0 = 0.f, s1 = 0.f;
        const int pxl = pxb + nt * 8 + (lane & 3) * 2;
        #pragma unroll
        for (int mt = 0; mt < 4; mt++) {
            int oc0 = ocb + mt * 16 + (lane >> 2);
            int oc1 = oc0 + 8;
            float f0 = acc[mt][nt][0] * scl[oc0] + shl[oc0];
            float f1 = acc[mt][nt][1] * scl[oc0] + shl[oc0];
            float f2 = acc[mt][nt][2] * scl[oc1] + shl[oc1];
            float f3 = acc[mt][nt][3] * scl[oc1] + shl[oc1];
            s0 += awl[oc0] * f0 + awl[oc1] * f2;
            s1 += awl[oc0] * f1 + awl[oc1] * f3;
            float* o0 = out + (((size_t)b * Cn + oc0) << 16) + h * 256 + px0 + pxl;
            float* o1 = out + (((size_t)b * Cn + oc1) << 16) + h * 256 + px0 + pxl;
            *(float2*)o0 = make_float2(f0, f1);
            *(float2*)o1 = make_float2(f2, f3);
        }
        s0 += __shfl_xor_sync(0xffffffffu, s0, 4);
        s0 += __shfl_xor_sync(0xffffffffu, s0, 8);
        s0 += __shfl_xor_sync(0xffffffffu, s0, 16);
        s1 += __shfl_xor_sync(0xffffffffu, s1, 4);
        s1 += __shfl_xor_sync(0xffffffffu, s1, 8);
        s1 += __shfl_xor_sync(0xffffffffu, s1, 16);
        if (lane < 4) {
            attbuf[warpM * 128 + pxb + nt * 8 + lane * 2]     = s0;
            attbuf[warpM * 128 + pxb + nt * 8 + lane * 2 + 1] = s1;
        }
    }
    __syncthreads();

    if (tid < 128) {
        int px = px0 + tid;
        float pa = attbuf[tid];
        float pb = attbuf[128 + tid];
        float ghv = fabsf((float)h - 128.f + 0.5f) * (1.f / 128.f);
        float gwv = fabsf((float)px - 128.f + 0.5f) * (1.f / 128.f);
        float raA = pa + attab[0]    + attaw[64] * ghv + attaw[65] * gwv;
        float raB = pb + attbbias[0] + attbw[64] * ghv + attbw[65] * gwv;
        float aa = (raA - abnam[0]) * (abnag[0] * rsqrtf(abnav[0] + 1e-5f)) + abnabt[0];
        float ab = (raB - abnbm[0]) * (abnbg[0] * rsqrtf(abnbv[0] + 1e-5f)) + abnbbt[0];
        size_t pi = ((size_t)b * Hn + h) * Wn + px;
        g_att[0][pi] = aa;
        g_att[1][pi] = ab;
    }
}

// ---------------------------------------------------------------------------
// Pass 2: 3x3 attention conv over [att, gh, gw, pr] + sigmoid, scale out.
// ---------------------------------------------------------------------------
__global__ __launch_bounds__(256)
void pass2_attn_scale(
    const float* __restrict__ wA, const float* __restrict__ wB,
    const float* __restrict__ s1p, const float* __restrict__ s2p,
    float* __restrict__ out)
{
    int t = blockIdx.x * 256 + threadIdx.x;
    int b = t >> 14, rem = t & 16383, h = rem >> 6, w4 = (rem & 63) << 2;

    const float ghmax = 127.5f / 128.f, ghmin = 0.5f / 128.f;
    float prmax = sqrtf(ghmax * ghmax + ghmax * ghmax);
    float prmin = sqrtf(ghmin * ghmin + ghmin * ghmin);
    float kk = 2.f / (prmax - prmin);
    float c0 = 1.f - prmax * kk;

    const float* attA = g_att[0] + (size_t)b * Hn * Wn;
    const float* attB = g_att[1] + (size_t)b * Hn * Wn;

    float sA[4] = {0.f, 0.f, 0.f, 0.f}, sB[4] = {0.f, 0.f, 0.f, 0.f};
    #pragma unroll
    for (int kh = 0; kh < 3; kh++) {
        int ih = h + kh - 1;
        if ((unsigned)ih >= (unsigned)Hn) continue;
        float ghv = fabsf((float)ih - 128.f + 0.5f) * (1.f / 128.f);
        #pragma unroll
        for (int kw = 0; kw < 3; kw++) {
            int ti = kh * 3 + kw;
            float wa0 = wA[ti], wa1 = wA[9 + ti], wa2 = wA[18 + ti], wa3 = wA[27 + ti];
            float wb0 = wB[ti], wb1 = wB[9 + ti], wb2 = wB[18 + ti], wb3 = wB[27 + ti];
            #pragma unroll
            for (int i = 0; i < 4; i++) {
                int jw = w4 + i + kw - 1;
                if ((unsigned)jw >= (unsigned)Wn) continue;
                float gwv = fabsf((float)jw - 128.f + 0.5f) * (1.f / 128.f);
                float pr = kk * sqrtf(ghv * ghv + gwv * gwv) + c0;
                float av = attA[(size_t)ih * Wn + jw];
                float bv = attB[(size_t)ih * Wn + jw];
                sA[i] += wa0 * av + wa1 * ghv + wa2 * gwv + wa3 * pr;
                sB[i] += wb0 * bv + wb1 * ghv + wb2 * gwv + wb3 * pr;
            }
        }
    }
    float s1 = s1p[0], s2 = s2p[0];
    float ma[4], mb2[4];
    #pragma unroll
    for (int i = 0; i < 4; i++) {
        ma[i]  = s1 / (1.f + expf(-sA[i]));
        mb2[i] = s2 / (1.f + expf(-sB[i]));
    }
    float* base = out + (((size_t)b * Cn) * Hn + h) * Wn + w4;
    #pragma unroll 1
    for (int c = 0; c < Cn; c++) {
        float4* p = (float4*)(base + (size_t)c * Hn * Wn);
        float4 v = *p;
        const float* m = (c < 64) ? ma : mb2;
        v.x *= m[0]; v.y *= m[1]; v.z *= m[2]; v.w *= m[3];
        *p = v;
    }
}

extern "C" void kernel_launch(void* const* d_in, const int* in_sizes, int n_in,
                              void* d_out, int out_size) {
    (void)in_sizes; (void)n_in; (void)out_size;
    const float* P[29];
    for (int i = 0; i < 29; i++) P[i] = (const float*)d_in[i];
    float* out = (float*)d_out;

    cudaFuncSetAttribute(pass1_mma, cudaFuncAttributeMaxDynamicSharedMemorySize, SMEM_BYTES);

    dim3 gx(8, 256, 4);
    xprep<<<gx, 256>>>(P[0]);
    wprep<<<(9 * 128 * 128 + 255) / 256, 256>>>(P[1], P[3]);
    dim3 g1(2, 256, 4);
    pass1_mma<<<g1, 256, SMEM_BYTES>>>(
        P[2], P[4],                   // conv biases a, b
        P[5], P[6], P[7], P[8],       // bn a
        P[9], P[10], P[11], P[12],    // bn b
        P[13], P[14], P[15], P[16],   // att 1x1 w/b a, b
        P[17], P[18], P[19], P[20],   // att bn a
        P[21], P[22], P[23], P[24],   // att bn b
        out);
    pass2_attn_scale<<<(Bn * Hn * Wn / 4) / 256, 256>>>(P[25], P[26], P[27], P[28], out);
}

// round 5
// speedup vs baseline: 3.8529x; 1.2446x over previous
#include <cuda_runtime.h>
#include <cuda_bf16.h>
#include <cstdint>
#include <math.h>

constexpr int Bn = 4, Cn = 128, Hn = 256, Wn = 256;

// ---- device scratch (static; no runtime allocs) ----
static __device__ float g_att[2][(size_t)Bn * Hn * Wn];                              // 2 MB
static __device__ __align__(16) unsigned char g_xnhwc[(size_t)Bn * Hn * Wn * 512];   // 128 MB [b][h][w][hi128|lo128] bf16
static __device__ __align__(16) unsigned char g_w[(size_t)9 * 2 * 128 * 128 * 2];    // 576 KB [tap][hi/lo][oc][ic] bf16

__device__ __forceinline__ unsigned short bf16_bits(__nv_bfloat16 h) {
    return *reinterpret_cast<unsigned short*>(&h);
}
__device__ __forceinline__ uint32_t smem_u32(const void* p) {
    uint32_t a;
    asm("{ .reg .u64 t; cvta.to.shared.u64 t, %1; cvt.u32.u64 %0, t; }" : "=r"(a) : "l"(p));
    return a;
}
__device__ __forceinline__ void ldsm_x4(uint32_t* r, uint32_t addr) {
    asm volatile("ldmatrix.sync.aligned.m8n8.x4.shared.b16 {%0,%1,%2,%3}, [%4];"
                 : "=r"(r[0]), "=r"(r[1]), "=r"(r[2]), "=r"(r[3]) : "r"(addr));
}
__device__ __forceinline__ void mma16816(float* d, const uint32_t* a, const uint32_t* b) {
    asm volatile(
        "mma.sync.aligned.m16n8k16.row.col.f32.bf16.bf16.f32 "
        "{%0,%1,%2,%3}, {%4,%5,%6,%7}, {%8,%9}, {%0,%1,%2,%3};"
        : "+f"(d[0]), "+f"(d[1]), "+f"(d[2]), "+f"(d[3])
        : "r"(a[0]), "r"(a[1]), "r"(a[2]), "r"(a[3]), "r"(b[0]), "r"(b[1]));
}
__device__ __forceinline__ void cp16(uint32_t dst, const void* src, bool ok) {
    int sz = ok ? 16 : 0;   // src-size 0 => zero-fill (halo / padded rows)
    asm volatile("cp.async.cg.shared.global [%0], [%1], 16, %2;"
                 :: "r"(dst), "l"(src), "r"(sz) : "memory");
}
__device__ __forceinline__ void cp_commit() {
    asm volatile("cp.async.commit_group;" ::: "memory");
}
template <int N>
__device__ __forceinline__ void cp_wait() {
    asm volatile("cp.async.wait_group %0;" :: "n"(N) : "memory");
}

// ---------------------------------------------------------------------------
// Setup 1: x NCHW fp32 -> NHWC bf16 hi/lo  [b][h][w][hi 128 | lo 128]
// ---------------------------------------------------------------------------
__global__ __launch_bounds__(256)
void xprep(const float* __restrict__ x) {
    __shared__ float tile[128][33];
    int wt = blockIdx.x, hh = blockIdx.y, b = blockIdx.z;
    int t = threadIdx.x, warp = t >> 5, lane = t & 31;
    const float* src = x + (((size_t)b * Cn + warp * 16) * Hn + hh) * Wn + wt * 32 + lane;
    #pragma unroll
    for (int k = 0; k < 16; k++) tile[warp * 16 + k][lane] = src[(size_t)k * Hn * Wn];
    __syncthreads();
    int px = t >> 3, seg = t & 7, icb = seg * 16;
    unsigned int hiv[8], lov[8];
    #pragma unroll
    for (int j = 0; j < 16; j += 2) {
        float v0 = tile[icb + j][px], v1 = tile[icb + j + 1][px];
        __nv_bfloat16 h0 = __float2bfloat16(v0), h1 = __float2bfloat16(v1);
        __nv_bfloat16 l0 = __float2bfloat16(v0 - __bfloat162float(h0));
        __nv_bfloat16 l1 = __float2bfloat16(v1 - __bfloat162float(h1));
        hiv[j >> 1] = (unsigned)bf16_bits(h0) | ((unsigned)bf16_bits(h1) << 16);
        lov[j >> 1] = (unsigned)bf16_bits(l0) | ((unsigned)bf16_bits(l1) << 16);
    }
    size_t p = ((size_t)b * Hn + hh) * Wn + wt * 32 + px;
    unsigned char* dst = g_xnhwc + p * 512;
    *(uint4*)(dst + icb * 2)            = make_uint4(hiv[0], hiv[1], hiv[2], hiv[3]);
    *(uint4*)(dst + icb * 2 + 16)       = make_uint4(hiv[4], hiv[5], hiv[6], hiv[7]);
    *(uint4*)(dst + 256 + icb * 2)      = make_uint4(lov[0], lov[1], lov[2], lov[3]);
    *(uint4*)(dst + 256 + icb * 2 + 16) = make_uint4(lov[4], lov[5], lov[6], lov[7]);
}

// ---------------------------------------------------------------------------
// Setup 2: weights -> g_w[tap][part][oc][ic] bf16 (hi part 0, lo part 1)
// ---------------------------------------------------------------------------
__global__ __launch_bounds__(256)
void wprep(const float* __restrict__ wa, const float* __restrict__ wb) {
    int id = blockIdx.x * 256 + threadIdx.x;
    if (id >= 9 * 128 * 128) return;
    int tap = id / 16384, rem = id & 16383, oc = rem >> 7, ic = rem & 127;
    float w = (oc < 64) ? wa[((size_t)oc * 128 + ic) * 9 + tap]
                        : wb[((size_t)(oc - 64) * 128 + ic) * 9 + tap];
    __nv_bfloat16 hi = __float2bfloat16(w);
    __nv_bfloat16 lo = __float2bfloat16(w - __bfloat162float(hi));
    unsigned char* b0 = g_w + (((size_t)tap * 2 + 0) * 128 + oc) * 256 + ic * 2;
    unsigned char* b1 = g_w + (((size_t)tap * 2 + 1) * 128 + oc) * 256 + ic * 2;
    *(unsigned short*)b0 = bf16_bits(hi);
    *(unsigned short*)b1 = bf16_bits(lo);
}

// ---------------------------------------------------------------------------
// Pass 1: mma.sync bf16 hi/lo implicit-GEMM conv, cp.async pipelined.
// CTA = 128 oc x 128 px. 8 warps: 2(oc) x 4(px).
// smem: W double buffer (2 x 64KB), X single buffer (66.5KB).
// ---------------------------------------------------------------------------
constexpr int SM_W    = 0;           // buf s at SM_W + s*65536; WH at +0, WL at +32768
constexpr int SM_XH   = 131072;      // 130 x 256B = 33280
constexpr int SM_XL   = 164352;      // 33280
constexpr int SM_LUT  = 197632;      // 3 x 128 f32 = 1536
constexpr int SM_ATT  = 199168;      // 2 x 128 f32 = 1024
constexpr int SMEM_BYTES = 200192;

__device__ __forceinline__ void stage_X(uint32_t sb32, const unsigned char* xbase,
                                        int ih, int px0, int tid) {
    const bool rowok = (unsigned)ih < (unsigned)Hn;
    const unsigned char* xrow = xbase + (size_t)(ih & 255) * (Wn * 512);
    for (int idx = tid; idx < 130 * 16; idx += 256) {
        int r = idx >> 4, c = idx & 15;
        int g = px0 - 1 + r;
        bool ok = rowok && ((unsigned)g < (unsigned)Wn);
        const unsigned char* src = xrow + (size_t)(g & 255) * 512 + c * 16;
        uint32_t off = (uint32_t)(r * 256 + ((c ^ (r & 7)) << 4));
        cp16(sb32 + SM_XH + off, src, ok);
        cp16(sb32 + SM_XL + off, src + 256, ok);
    }
}
__device__ __forceinline__ void stage_W(uint32_t sb32, int tap, int bufsel, int tid) {
    const unsigned char* wsrc = g_w + (size_t)tap * 65536;
    uint32_t wb = sb32 + SM_W + bufsel * 65536;
    for (int idx = tid; idx < 128 * 16; idx += 256) {
        int r = idx >> 4, c = idx & 15;
        uint32_t off = (uint32_t)(r * 256 + ((c ^ (r & 7)) << 4));
        cp16(wb + off,         wsrc + r * 256 + c * 16,         true);
        cp16(wb + 32768 + off, wsrc + 32768 + r * 256 + c * 16, true);
    }
}

__global__ __launch_bounds__(256)
void pass1_mma(
    const float* __restrict__ ba, const float* __restrict__ bb,
    const float* __restrict__ bnag, const float* __restrict__ bnabt,
    const float* __restrict__ bnam, const float* __restrict__ bnav,
    const float* __restrict__ bnbg, const float* __restrict__ bnbbt,
    const float* __restrict__ bnbm, const float* __restrict__ bnbv,
    const float* __restrict__ attaw, const float* __restrict__ attab,
    const float* __restrict__ attbw, const float* __restrict__ attbbias,
    const float* __restrict__ abnag, const float* __restrict__ abnabt,
    const float* __restrict__ abnam, const float* __restrict__ abnav,
    const float* __restrict__ abnbg, const float* __restrict__ abnbbt,
    const float* __restrict__ abnbm, const float* __restrict__ abnbv,
    float* __restrict__ out)
{
    extern __shared__ char sb[];
    const uint32_t sb32 = smem_u32(sb);

    const int tid = threadIdx.x, wid = tid >> 5, lane = tid & 31;
    const int warpM = wid & 1, warpN = wid >> 1;
    const int px0 = (blockIdx.x & 1) * 128;
    const int h = blockIdx.y, b = blockIdx.z;
    const int ocb = warpM * 64, pxb = warpN * 32;
    const unsigned char* xbase = g_xnhwc + (size_t)b * Hn * (Wn * 512);

    // per-oc BN/attention LUTs (smem region untouched by staging)
    if (tid < 128) {
        int oc = tid; bool isB = oc >= 64; int ol = oc & 63;
        float g  = isB ? bnbg[ol]  : bnag[ol];
        float bt = isB ? bnbbt[ol] : bnabt[ol];
        float mu = isB ? bnbm[ol]  : bnam[ol];
        float vr = isB ? bnbv[ol]  : bnav[ol];
        float cb = isB ? bb[ol]    : ba[ol];
        float sc = g * rsqrtf(vr + 1e-3f);
        float* lut = (float*)(sb + SM_LUT);
        lut[oc]       = sc;
        lut[128 + oc] = (cb - mu) * sc + bt;
        lut[256 + oc] = isB ? attbw[ol] : attaw[ol];
    }

    float acc[4][4][4];
    #pragma unroll
    for (int i = 0; i < 4; i++)
        #pragma unroll
        for (int j = 0; j < 4; j++)
            #pragma unroll
            for (int k = 0; k < 4; k++) acc[i][j][k] = 0.f;

    // -------- pipeline prologue --------
    stage_X(sb32, xbase, h - 1, px0, tid);   // kh = 0
    stage_W(sb32, 0, 0, tid);
    cp_commit();                              // {X(kh0), W0}
    stage_W(sb32, 1, 1, tid);
    cp_commit();                              // {W1}

    // -------- 9-tap mainloop --------
    #pragma unroll 1
    for (int t = 0; t < 9; t++) {
        if (t == 8) cp_wait<0>(); else cp_wait<1>();
        __syncthreads();

        const int kw = t - (t / 3) * 3;
        const uint32_t wbase = sb32 + SM_W + (uint32_t)(t & 1) * 65536;

        #pragma unroll 1
        for (int kc = 0; kc < 8; kc++) {
            const int cA = kc * 2;
            uint32_t ah[4][4], alw[4][4];
            #pragma unroll
            for (int mt = 0; mt < 4; mt++) {
                int mrow = ocb + mt * 16 + (lane & 15);
                int cc = cA + (lane >> 4);
                uint32_t off = (uint32_t)(mrow * 256 + ((cc ^ (mrow & 7)) << 4));
                ldsm_x4(ah[mt],  wbase + off);
                ldsm_x4(alw[mt], wbase + 32768 + off);
            }
            uint32_t bh[2][4], bl[2][4];
            #pragma unroll
            for (int ntp = 0; ntp < 2; ntp++) {
                int prow = pxb + ntp * 16 + (lane & 7) + ((lane & 16) ? 8 : 0) + kw;
                int cc = cA + ((lane >> 3) & 1);
                uint32_t off = (uint32_t)(prow * 256 + ((cc ^ (prow & 7)) << 4));
                ldsm_x4(bh[ntp], sb32 + SM_XH + off);
                ldsm_x4(bl[ntp], sb32 + SM_XL + off);
            }
            #pragma unroll
            for (int mt = 0; mt < 4; mt++)
                #pragma unroll
                for (int nt = 0; nt < 4; nt++) {
                    float* d = acc[mt][nt];
                    const uint32_t* pbh = &bh[nt >> 1][(nt & 1) * 2];
                    const uint32_t* pbl = &bl[nt >> 1][(nt & 1) * 2];
                    mma16816(d, ah[mt],  pbh);   // xh * wh
                    mma16816(d, alw[mt], pbh);   // xh * wl
                    mma16816(d, ah[mt],  pbl);   // xl * wh
                }
        }
        __syncthreads();   // compute done before buffers are overwritten

        if (t < 8) {
            if (((t + 1) % 3) == 0) {            // next tap starts a new kh
                stage_X(sb32, xbase, h + (t + 1) / 3 - 1, px0, tid);
                cp_commit();
            }
            if (t + 2 <= 8) {
                stage_W(sb32, t + 2, t & 1, tid);
                cp_commit();
            }
        }
    }

    // ---- epilogue: BN + store f + 1x1 attention partial ----
    const float* scl = (const float*)(sb + SM_LUT);
    const float* shl = scl + 128;
    const float* awl = scl + 256;
    float* attbuf = (float*)(sb + SM_ATT);

    #pragma unroll
    for (int nt = 0; nt < 4; nt++) {
        float s0 = 0.f, s1 = 0.f;
        const int pxl = pxb + nt * 8 + (lane & 3) * 2;
        #pragma unroll
        for (int mt = 0; mt < 4; mt++) {
            int oc0 = ocb + mt * 16 + (lane >> 2);
            int oc1 = oc0 + 8;
            float f0 = acc[mt][nt][0] * scl[oc0] + shl[oc0];
            float f1 = acc[mt][nt][1] * scl[oc0] + shl[oc0];
            float f2 = acc[mt][nt][2] * scl[oc1] + shl[oc1];
            float f3 = acc[mt][nt][3] * scl[oc1] + shl[oc1];
            s0 += awl[oc0] * f0 + awl[oc1] * f2;
            s1 += awl[oc0] * f1 + awl[oc1] * f3;
            float* o0 = out + (((size_t)b * Cn + oc0) << 16) + h * 256 + px0 + pxl;
            float* o1 = out + (((size_t)b * Cn + oc1) << 16) + h * 256 + px0 + pxl;
            *(float2*)o0 = make_float2(f0, f1);
            *(float2*)o1 = make_float2(f2, f3);
        }
        s0 += __shfl_xor_sync(0xffffffffu, s0, 4);
        s0 += __shfl_xor_sync(0xffffffffu, s0, 8);
        s0 += __shfl_xor_sync(0xffffffffu, s0, 16);
        s1 += __shfl_xor_sync(0xffffffffu, s1, 4);
        s1 += __shfl_xor_sync(0xffffffffu, s1, 8);
        s1 += __shfl_xor_sync(0xffffffffu, s1, 16);
        if (lane < 4) {
            attbuf[warpM * 128 + pxb + nt * 8 + lane * 2]     = s0;
            attbuf[warpM * 128 + pxb + nt * 8 + lane * 2 + 1] = s1;
        }
    }
    __syncthreads();

    if (tid < 128) {
        int px = px0 + tid;
        float pa = attbuf[tid];
        float pb = attbuf[128 + tid];
        float ghv = fabsf((float)h - 128.f + 0.5f) * (1.f / 128.f);
        float gwv = fabsf((float)px - 128.f + 0.5f) * (1.f / 128.f);
        float raA = pa + attab[0]    + attaw[64] * ghv + attaw[65] * gwv;
        float raB = pb + attbbias[0] + attbw[64] * ghv + attbw[65] * gwv;
        float aa = (raA - abnam[0]) * (abnag[0] * rsqrtf(abnav[0] + 1e-5f)) + abnabt[0];
        float ab = (raB - abnbm[0]) * (abnbg[0] * rsqrtf(abnbv[0] + 1e-5f)) + abnbbt[0];
        size_t pi = ((size_t)b * Hn + h) * Wn + px;
        g_att[0][pi] = aa;
        g_att[1][pi] = ab;
    }
}

// ---------------------------------------------------------------------------
// Pass 2: 3x3 attention conv + sigmoid, scale out.
// grid (256, 4): blockIdx.y selects a 32-channel chunk (4x parallelism).
// ---------------------------------------------------------------------------
__global__ __launch_bounds__(256)
void pass2_attn_scale(
    const float* __restrict__ wA, const float* __restrict__ wB,
    const float* __restrict__ s1p, const float* __restrict__ s2p,
    float* __restrict__ out)
{
    int t = blockIdx.x * 256 + threadIdx.x;
    int b = t >> 14, rem = t & 16383, h = rem >> 6, w4 = (rem & 63) << 2;
    const int cch = blockIdx.y;           // 0..3 -> channels [cch*32, cch*32+32)
    const bool branchA = (cch < 2);

    const float ghmax = 127.5f / 128.f, ghmin = 0.5f / 128.f;
    float prmax = sqrtf(ghmax * ghmax + ghmax * ghmax);
    float prmin = sqrtf(ghmin * ghmin + ghmin * ghmin);
    float kk = 2.f / (prmax - prmin);
    float c0 = 1.f - prmax * kk;

    const float* att = g_att[branchA ? 0 : 1] + (size_t)b * Hn * Wn;
    const float* wgt = branchA ? wA : wB;
    float scale = branchA ? s1p[0] : s2p[0];

    float s[4] = {0.f, 0.f, 0.f, 0.f};
    #pragma unroll
    for (int kh = 0; kh < 3; kh++) {
        int ih = h + kh - 1;
        if ((unsigned)ih >= (unsigned)Hn) continue;
        float ghv = fabsf((float)ih - 128.f + 0.5f) * (1.f / 128.f);
        #pragma unroll
        for (int kw = 0; kw < 3; kw++) {
            int ti = kh * 3 + kw;
            float w0 = wgt[ti], w1 = wgt[9 + ti], w2 = wgt[18 + ti], w3 = wgt[27 + ti];
            #pragma unroll
            for (int i = 0; i < 4; i++) {
                int jw = w4 + i + kw - 1;
                if ((unsigned)jw >= (unsigned)Wn) continue;
                float gwv = fabsf((float)jw - 128.f + 0.5f) * (1.f / 128.f);
                float pr = kk * sqrtf(ghv * ghv + gwv * gwv) + c0;
                float av = att[(size_t)ih * Wn + jw];
                s[i] += w0 * av + w1 * ghv + w2 * gwv + w3 * pr;
            }
        }
    }
    float m[4];
    #pragma unroll
    for (int i = 0; i < 4; i++) m[i] = scale / (1.f + expf(-s[i]));

    float* base = out + (((size_t)b * Cn + cch * 32) * Hn + h) * Wn + w4;
    #pragma unroll 4
    for (int c = 0; c < 32; c++) {
        float4* p = (float4*)(base + (size_t)c * Hn * Wn);
        float4 v = *p;
        v.x *= m[0]; v.y *= m[1]; v.z *= m[2]; v.w *= m[3];
        *p = v;
    }
}

extern "C" void kernel_launch(void* const* d_in, const int* in_sizes, int n_in,
                              void* d_out, int out_size) {
    (void)in_sizes; (void)n_in; (void)out_size;
    const float* P[29];
    for (int i = 0; i < 29; i++) P[i] = (const float*)d_in[i];
    float* out = (float*)d_out;

    cudaFuncSetAttribute(pass1_mma, cudaFuncAttributeMaxDynamicSharedMemorySize, SMEM_BYTES);

    dim3 gx(8, 256, 4);
    xprep<<<gx, 256>>>(P[0]);
    wprep<<<(9 * 128 * 128 + 255) / 256, 256>>>(P[1], P[3]);
    dim3 g1(2, 256, 4);
    pass1_mma<<<g1, 256, SMEM_BYTES>>>(
        P[2], P[4],                   // conv biases a, b
        P[5], P[6], P[7], P[8],       // bn a
        P[9], P[10], P[11], P[12],    // bn b
        P[13], P[14], P[15], P[16],   // att 1x1 w/b a, b
        P[17], P[18], P[19], P[20],   // att bn a
        P[21], P[22], P[23], P[24],   // att bn b
        out);
    dim3 g2((Bn * Hn * Wn / 4) / 256, 4);
    pass2_attn_scale<<<g2, 256>>>(P[25], P[26], P[27], P[28], out);
}

// round 6
// speedup vs baseline: 5.0565x; 1.3124x over previous
#include <cuda_runtime.h>
#include <cuda_fp16.h>
#include <cstdint>
#include <math.h>

constexpr int Bn = 4, Cn = 128, Hn = 256, Wn = 256;

// ---- device scratch (static; no runtime allocs) ----
static __device__ float g_att[2][(size_t)Bn * Hn * Wn];                              // 2 MB
static __device__ __align__(16) unsigned char g_xnhwc[(size_t)Bn * Hn * Wn * 512];   // 128 MB [b][h][w][hi128|lo128] fp16
static __device__ __align__(16) unsigned char g_w[(size_t)9 * 128 * 128 * 2];        // 288 KB [tap][oc][ic] fp16

__device__ __forceinline__ unsigned short h_bits(__half h) {
    return __half_as_ushort(h);
}
__device__ __forceinline__ uint32_t smem_u32(const void* p) {
    uint32_t a;
    asm("{ .reg .u64 t; cvta.to.shared.u64 t, %1; cvt.u32.u64 %0, t; }" : "=r"(a) : "l"(p));
    return a;
}
__device__ __forceinline__ void ldsm_x4(uint32_t* r, uint32_t addr) {
    asm volatile("ldmatrix.sync.aligned.m8n8.x4.shared.b16 {%0,%1,%2,%3}, [%4];"
                 : "=r"(r[0]), "=r"(r[1]), "=r"(r[2]), "=r"(r[3]) : "r"(addr));
}
__device__ __forceinline__ void mma16816h(float* d, const uint32_t* a, const uint32_t* b) {
    asm volatile(
        "mma.sync.aligned.m16n8k16.row.col.f32.f16.f16.f32 "
        "{%0,%1,%2,%3}, {%4,%5,%6,%7}, {%8,%9}, {%0,%1,%2,%3};"
        : "+f"(d[0]), "+f"(d[1]), "+f"(d[2]), "+f"(d[3])
        : "r"(a[0]), "r"(a[1]), "r"(a[2]), "r"(a[3]), "r"(b[0]), "r"(b[1]));
}
__device__ __forceinline__ void cp16(uint32_t dst, const void* src, bool ok) {
    int sz = ok ? 16 : 0;   // src-size 0 => zero-fill (halo / padded rows)
    asm volatile("cp.async.cg.shared.global [%0], [%1], 16, %2;"
                 :: "r"(dst), "l"(src), "r"(sz) : "memory");
}
__device__ __forceinline__ void cp_commit() {
    asm volatile("cp.async.commit_group;" ::: "memory");
}
template <int N>
__device__ __forceinline__ void cp_wait() {
    asm volatile("cp.async.wait_group %0;" :: "n"(N) : "memory");
}

// ---------------------------------------------------------------------------
// Setup 1: x NCHW fp32 -> NHWC fp16 hi/lo  [b][h][w][hi 128 | lo 128]
// ---------------------------------------------------------------------------
__global__ __launch_bounds__(256)
void xprep(const float* __restrict__ x) {
    __shared__ float tile[128][33];
    int wt = blockIdx.x, hh = blockIdx.y, b = blockIdx.z;
    int t = threadIdx.x, warp = t >> 5, lane = t & 31;
    const float* src = x + (((size_t)b * Cn + warp * 16) * Hn + hh) * Wn + wt * 32 + lane;
    #pragma unroll
    for (int k = 0; k < 16; k++) tile[warp * 16 + k][lane] = src[(size_t)k * Hn * Wn];
    __syncthreads();
    int px = t >> 3, seg = t & 7, icb = seg * 16;
    unsigned int hiv[8], lov[8];
    #pragma unroll
    for (int j = 0; j < 16; j += 2) {
        float v0 = tile[icb + j][px], v1 = tile[icb + j + 1][px];
        __half h0 = __float2half_rn(v0), h1 = __float2half_rn(v1);
        __half l0 = __float2half_rn(v0 - __half2float(h0));
        __half l1 = __float2half_rn(v1 - __half2float(h1));
        hiv[j >> 1] = (unsigned)h_bits(h0) | ((unsigned)h_bits(h1) << 16);
        lov[j >> 1] = (unsigned)h_bits(l0) | ((unsigned)h_bits(l1) << 16);
    }
    size_t p = ((size_t)b * Hn + hh) * Wn + wt * 32 + px;
    unsigned char* dst = g_xnhwc + p * 512;
    *(uint4*)(dst + icb * 2)            = make_uint4(hiv[0], hiv[1], hiv[2], hiv[3]);
    *(uint4*)(dst + icb * 2 + 16)       = make_uint4(hiv[4], hiv[5], hiv[6], hiv[7]);
    *(uint4*)(dst + 256 + icb * 2)      = make_uint4(lov[0], lov[1], lov[2], lov[3]);
    *(uint4*)(dst + 256 + icb * 2 + 16) = make_uint4(lov[4], lov[5], lov[6], lov[7]);
}

// ---------------------------------------------------------------------------
// Setup 2: weights -> g_w[tap][oc][ic] fp16 (single part)
// ---------------------------------------------------------------------------
__global__ __launch_bounds__(256)
void wprep(const float* __restrict__ wa, const float* __restrict__ wb) {
    int id = blockIdx.x * 256 + threadIdx.x;
    if (id >= 9 * 128 * 128) return;
    int tap = id / 16384, rem = id & 16383, oc = rem >> 7, ic = rem & 127;
    float w = (oc < 64) ? wa[((size_t)oc * 128 + ic) * 9 + tap]
                        : wb[((size_t)(oc - 64) * 128 + ic) * 9 + tap];
    *(unsigned short*)(g_w + (((size_t)tap * 128 + oc) * 128 + ic) * 2) =
        h_bits(__float2half_rn(w));
}

// ---------------------------------------------------------------------------
// Pass 1: mma.sync fp16 hi/lo implicit-GEMM conv, cp.async pipelined.
// CTA = 128 oc x 128 px. 8 warps: 2(oc) x 4(px). 2 MMAs per k16.
// smem: W double buffer (2 x 32KB), X single buffer (66.5KB).
// ---------------------------------------------------------------------------
constexpr int SM_W    = 0;           // buf s at SM_W + s*32768
constexpr int SM_XH   = 65536;       // 130 x 256B = 33280
constexpr int SM_XL   = 98816;       // 33280
constexpr int SM_LUT  = 132096;      // 3 x 128 f32 = 1536
constexpr int SM_ATT  = 133632;      // 2 x 128 f32 = 1024
constexpr int SMEM_BYTES = 134656;

__device__ __forceinline__ void stage_X(uint32_t sb32, const unsigned char* xbase,
                                        int ih, int px0, int tid) {
    const bool rowok = (unsigned)ih < (unsigned)Hn;
    const unsigned char* xrow = xbase + (size_t)(ih & 255) * (Wn * 512);
    for (int idx = tid; idx < 130 * 16; idx += 256) {
        int r = idx >> 4, c = idx & 15;
        int g = px0 - 1 + r;
        bool ok = rowok && ((unsigned)g < (unsigned)Wn);
        const unsigned char* src = xrow + (size_t)(g & 255) * 512 + c * 16;
        uint32_t off = (uint32_t)(r * 256 + ((c ^ (r & 7)) << 4));
        cp16(sb32 + SM_XH + off, src, ok);
        cp16(sb32 + SM_XL + off, src + 256, ok);
    }
}
__device__ __forceinline__ void stage_W(uint32_t sb32, int tap, int bufsel, int tid) {
    const unsigned char* wsrc = g_w + (size_t)tap * 32768;
    uint32_t wb = sb32 + SM_W + bufsel * 32768;
    for (int idx = tid; idx < 128 * 16; idx += 256) {
        int r = idx >> 4, c = idx & 15;
        uint32_t off = (uint32_t)(r * 256 + ((c ^ (r & 7)) << 4));
        cp16(wb + off, wsrc + r * 256 + c * 16, true);
    }
}

__global__ __launch_bounds__(256)
void pass1_mma(
    const float* __restrict__ ba, const float* __restrict__ bb,
    const float* __restrict__ bnag, const float* __restrict__ bnabt,
    const float* __restrict__ bnam, const float* __restrict__ bnav,
    const float* __restrict__ bnbg, const float* __restrict__ bnbbt,
    const float* __restrict__ bnbm, const float* __restrict__ bnbv,
    const float* __restrict__ attaw, const float* __restrict__ attab,
    const float* __restrict__ attbw, const float* __restrict__ attbbias,
    const float* __restrict__ abnag, const float* __restrict__ abnabt,
    const float* __restrict__ abnam, const float* __restrict__ abnav,
    const float* __restrict__ abnbg, const float* __restrict__ abnbbt,
    const float* __restrict__ abnbm, const float* __restrict__ abnbv,
    float* __restrict__ out)
{
    extern __shared__ char sb[];
    const uint32_t sb32 = smem_u32(sb);

    const int tid = threadIdx.x, wid = tid >> 5, lane = tid & 31;
    const int warpM = wid & 1, warpN = wid >> 1;
    const int px0 = (blockIdx.x & 1) * 128;
    const int h = blockIdx.y, b = blockIdx.z;
    const int ocb = warpM * 64, pxb = warpN * 32;
    const unsigned char* xbase = g_xnhwc + (size_t)b * Hn * (Wn * 512);

    // per-oc BN/attention LUTs
    if (tid < 128) {
        int oc = tid; bool isB = oc >= 64; int ol = oc & 63;
        float g  = isB ? bnbg[ol]  : bnag[ol];
        float bt = isB ? bnbbt[ol] : bnabt[ol];
        float mu = isB ? bnbm[ol]  : bnam[ol];
        float vr = isB ? bnbv[ol]  : bnav[ol];
        float cb = isB ? bb[ol]    : ba[ol];
        float sc = g * rsqrtf(vr + 1e-3f);
        float* lut = (float*)(sb + SM_LUT);
        lut[oc]       = sc;
        lut[128 + oc] = (cb - mu) * sc + bt;
        lut[256 + oc] = isB ? attbw[ol] : attaw[ol];
    }

    float acc[4][4][4];
    #pragma unroll
    for (int i = 0; i < 4; i++)
        #pragma unroll
        for (int j = 0; j < 4; j++)
            #pragma unroll
            for (int k = 0; k < 4; k++) acc[i][j][k] = 0.f;

    // -------- pipeline prologue --------
    stage_X(sb32, xbase, h - 1, px0, tid);   // kh = 0
    stage_W(sb32, 0, 0, tid);
    cp_commit();                              // {X(kh0), W0}
    stage_W(sb32, 1, 1, tid);
    cp_commit();                              // {W1}

    // -------- 9-tap mainloop --------
    #pragma unroll 1
    for (int t = 0; t < 9; t++) {
        if (t == 8) cp_wait<0>(); else cp_wait<1>();
        __syncthreads();

        const int kw = t - (t / 3) * 3;
        const uint32_t wbase = sb32 + SM_W + (uint32_t)(t & 1) * 32768;

        #pragma unroll 2
        for (int kc = 0; kc < 8; kc++) {
            const int cA = kc * 2;
            uint32_t ah[4][4];
            #pragma unroll
            for (int mt = 0; mt < 4; mt++) {
                int mrow = ocb + mt * 16 + (lane & 15);
                int cc = cA + (lane >> 4);
                uint32_t off = (uint32_t)(mrow * 256 + ((cc ^ (mrow & 7)) << 4));
                ldsm_x4(ah[mt], wbase + off);
            }
            uint32_t bh[2][4], bl[2][4];
            #pragma unroll
            for (int ntp = 0; ntp < 2; ntp++) {
                int prow = pxb + ntp * 16 + (lane & 7) + ((lane & 16) ? 8 : 0) + kw;
                int cc = cA + ((lane >> 3) & 1);
                uint32_t off = (uint32_t)(prow * 256 + ((cc ^ (prow & 7)) << 4));
                ldsm_x4(bh[ntp], sb32 + SM_XH + off);
                ldsm_x4(bl[ntp], sb32 + SM_XL + off);
            }
            #pragma unroll
            for (int mt = 0; mt < 4; mt++)
                #pragma unroll
                for (int nt = 0; nt < 4; nt++) {
                    float* d = acc[mt][nt];
                    const uint32_t* pbh = &bh[nt >> 1][(nt & 1) * 2];
                    const uint32_t* pbl = &bl[nt >> 1][(nt & 1) * 2];
                    mma16816h(d, ah[mt], pbh);   // xh * w
                    mma16816h(d, ah[mt], pbl);   // xl * w
                }
        }
        __syncthreads();   // compute done before buffers are overwritten

        if (t < 8) {
            if (((t + 1) % 3) == 0) {            // next tap starts a new kh
                stage_X(sb32, xbase, h + (t + 1) / 3 - 1, px0, tid);
                cp_commit();
            }
            if (t + 2 <= 8) {
                stage_W(sb32, t + 2, t & 1, tid);
                cp_commit();
            }
        }
    }

    // ---- epilogue: BN + store f + 1x1 attention partial ----
    const float* scl = (const float*)(sb + SM_LUT);
    const float* shl = scl + 128;
    const float* awl = scl + 256;
    float* attbuf = (float*)(sb + SM_ATT);

    #pragma unroll
    for (int nt = 0; nt < 4; nt++) {
        float s0 = 0.f, s1 = 0.f;
        const int pxl = pxb + nt * 8 + (lane & 3) * 2;
        #pragma unroll
        for (int mt = 0; mt < 4; mt++) {
            int oc0 = ocb + mt * 16 + (lane >> 2);
            int oc1 = oc0 + 8;
            float f0 = acc[mt][nt][0] * scl[oc0] + shl[oc0];
            float f1 = acc[mt][nt][1] * scl[oc0] + shl[oc0];
            float f2 = acc[mt][nt][2] * scl[oc1] + shl[oc1];
            float f3 = acc[mt][nt][3] * scl[oc1] + shl[oc1];
            s0 += awl[oc0] * f0 + awl[oc1] * f2;
            s1 += awl[oc0] * f1 + awl[oc1] * f3;
            float* o0 = out + (((size_t)b * Cn + oc0) << 16) + h * 256 + px0 + pxl;
            float* o1 = out + (((size_t)b * Cn + oc1) << 16) + h * 256 + px0 + pxl;
            *(float2*)o0 = make_float2(f0, f1);
            *(float2*)o1 = make_float2(f2, f3);
        }
        s0 += __shfl_xor_sync(0xffffffffu, s0, 4);
        s0 += __shfl_xor_sync(0xffffffffu, s0, 8);
        s0 += __shfl_xor_sync(0xffffffffu, s0, 16);
        s1 += __shfl_xor_sync(0xffffffffu, s1, 4);
        s1 += __shfl_xor_sync(0xffffffffu, s1, 8);
        s1 += __shfl_xor_sync(0xffffffffu, s1, 16);
        if (lane < 4) {
            attbuf[warpM * 128 + pxb + nt * 8 + lane * 2]     = s0;
            attbuf[warpM * 128 + pxb + nt * 8 + lane * 2 + 1] = s1;
        }
    }
    __syncthreads();

    if (tid < 128) {
        int px = px0 + tid;
        float pa = attbuf[tid];
        float pb = attbuf[128 + tid];
        float ghv = fabsf((float)h - 128.f + 0.5f) * (1.f / 128.f);
        float gwv = fabsf((float)px - 128.f + 0.5f) * (1.f / 128.f);
        float raA = pa + attab[0]    + attaw[64] * ghv + attaw[65] * gwv;
        float raB = pb + attbbias[0] + attbw[64] * ghv + attbw[65] * gwv;
        float aa = (raA - abnam[0]) * (abnag[0] * rsqrtf(abnav[0] + 1e-5f)) + abnabt[0];
        float ab = (raB - abnbm[0]) * (abnbg[0] * rsqrtf(abnbv[0] + 1e-5f)) + abnbbt[0];
        size_t pi = ((size_t)b * Hn + h) * Wn + px;
        g_att[0][pi] = aa;
        g_att[1][pi] = ab;
    }
}

// ---------------------------------------------------------------------------
// Pass 2: 3x3 attention conv + sigmoid, scale out.
// grid (256, 4): blockIdx.y selects a 32-channel chunk.
// ---------------------------------------------------------------------------
__global__ __launch_bounds__(256)
void pass2_attn_scale(
    const float* __restrict__ wA, const float* __restrict__ wB,
    const float* __restrict__ s1p, const float* __restrict__ s2p,
    float* __restrict__ out)
{
    int t = blockIdx.x * 256 + threadIdx.x;
    int b = t >> 14, rem = t & 16383, h = rem >> 6, w4 = (rem & 63) << 2;
    const int cch = blockIdx.y;           // 0..3 -> channels [cch*32, cch*32+32)
    const bool branchA = (cch < 2);

    const float ghmax = 127.5f / 128.f, ghmin = 0.5f / 128.f;
    float prmax = sqrtf(ghmax * ghmax + ghmax * ghmax);
    float prmin = sqrtf(ghmin * ghmin + ghmin * ghmin);
    float kk = 2.f / (prmax - prmin);
    float c0 = 1.f - prmax * kk;

    const float* att = g_att[branchA ? 0 : 1] + (size_t)b * Hn * Wn;
    const float* wgt = branchA ? wA : wB;
    float scale = branchA ? s1p[0] : s2p[0];

    float s[4] = {0.f, 0.f, 0.f, 0.f};
    #pragma unroll
    for (int kh = 0; kh < 3; kh++) {
        int ih = h + kh - 1;
        if ((unsigned)ih >= (unsigned)Hn) continue;
        float ghv = fabsf((float)ih - 128.f + 0.5f) * (1.f / 128.f);
        #pragma unroll
        for (int kw = 0; kw < 3; kw++) {
            int ti = kh * 3 + kw;
            float w0 = wgt[ti], w1 = wgt[9 + ti], w2 = wgt[18 + ti], w3 = wgt[27 + ti];
            #pragma unroll
            for (int i = 0; i < 4; i++) {
                int jw = w4 + i + kw - 1;
                if ((unsigned)jw >= (unsigned)Wn) continue;
                float gwv = fabsf((float)jw - 128.f + 0.5f) * (1.f / 128.f);
                float pr = kk * sqrtf(ghv * ghv + gwv * gwv) + c0;
                float av = att[(size_t)ih * Wn + jw];
                s[i] += w0 * av + w1 * ghv + w2 * gwv + w3 * pr;
            }
        }
    }
    float m[4];
    #pragma unroll
    for (int i = 0; i < 4; i++) m[i] = scale / (1.f + expf(-s[i]));

    float* base = out + (((size_t)b * Cn + cch * 32) * Hn + h) * Wn + w4;
    #pragma unroll 4
    for (int c = 0; c < 32; c++) {
        float4* p = (float4*)(base + (size_t)c * Hn * Wn);
        float4 v = *p;
        v.x *= m[0]; v.y *= m[1]; v.z *= m[2]; v.w *= m[3];
        *p = v;
    }
}

extern "C" void kernel_launch(void* const* d_in, const int* in_sizes, int n_in,
                              void* d_out, int out_size) {
    (void)in_sizes; (void)n_in; (void)out_size;
    const float* P[29];
    for (int i = 0; i < 29; i++) P[i] = (const float*)d_in[i];
    float* out = (float*)d_out;

    cudaFuncSetAttribute(pass1_mma, cudaFuncAttributeMaxDynamicSharedMemorySize, SMEM_BYTES);

    dim3 gx(8, 256, 4);
    xprep<<<gx, 256>>>(P[0]);
    wprep<<<(9 * 128 * 128 + 255) / 256, 256>>>(P[1], P[3]);
    dim3 g1(2, 256, 4);
    pass1_mma<<<g1, 256, SMEM_BYTES>>>(
        P[2], P[4],                   // conv biases a, b
        P[5], P[6], P[7], P[8],       // bn a
        P[9], P[10], P[11], P[12],    // bn b
        P[13], P[14], P[15], P[16],   // att 1x1 w/b a, b
        P[17], P[18], P[19], P[20],   // att bn a
        P[21], P[22], P[23], P[24],   // att bn b
        out);
    dim3 g2((Bn * Hn * Wn / 4) / 256, 4);
    pass2_attn_scale<<<g2, 256>>>(P[25], P[26], P[27], P[28], out);
}

// round 7
// speedup vs baseline: 8.3341x; 1.6482x over previous
#include <cuda_runtime.h>
#include <cuda_fp16.h>
#include <cstdint>
#include <math.h>

constexpr int Bn = 4, Cn = 128, Hn = 256, Wn = 256;

// ---- device scratch (static; no runtime allocs) ----
static __device__ float g_att[2][(size_t)Bn * Hn * Wn];                              // 2 MB
static __device__ __align__(16) unsigned char g_xnhwc[(size_t)Bn * Hn * Wn * 256];   // 64 MB [b][h][w][128 ic] fp16
static __device__ __align__(16) unsigned char g_w[(size_t)9 * 128 * 128 * 2];        // 288 KB [tap][oc][ic] fp16

__device__ __forceinline__ unsigned short h_bits(__half h) {
    return __half_as_ushort(h);
}
__device__ __forceinline__ uint32_t smem_u32(const void* p) {
    uint32_t a;
    asm("{ .reg .u64 t; cvta.to.shared.u64 t, %1; cvt.u32.u64 %0, t; }" : "=r"(a) : "l"(p));
    return a;
}
__device__ __forceinline__ void ldsm_x4(uint32_t* r, uint32_t addr) {
    asm volatile("ldmatrix.sync.aligned.m8n8.x4.shared.b16 {%0,%1,%2,%3}, [%4];"
                 : "=r"(r[0]), "=r"(r[1]), "=r"(r[2]), "=r"(r[3]) : "r"(addr));
}
__device__ __forceinline__ void mma16816h(float* d, const uint32_t* a, const uint32_t* b) {
    asm volatile(
        "mma.sync.aligned.m16n8k16.row.col.f32.f16.f16.f32 "
        "{%0,%1,%2,%3}, {%4,%5,%6,%7}, {%8,%9}, {%0,%1,%2,%3};"
        : "+f"(d[0]), "+f"(d[1]), "+f"(d[2]), "+f"(d[3])
        : "r"(a[0]), "r"(a[1]), "r"(a[2]), "r"(a[3]), "r"(b[0]), "r"(b[1]));
}
__device__ __forceinline__ void cp16(uint32_t dst, const void* src, bool ok) {
    int sz = ok ? 16 : 0;   // src-size 0 => zero-fill (halo / padded rows)
    asm volatile("cp.async.cg.shared.global [%0], [%1], 16, %2;"
                 :: "r"(dst), "l"(src), "r"(sz) : "memory");
}
__device__ __forceinline__ void cp_commit() {
    asm volatile("cp.async.commit_group;" ::: "memory");
}
template <int N>
__device__ __forceinline__ void cp_wait() {
    asm volatile("cp.async.wait_group %0;" :: "n"(N) : "memory");
}

// ---------------------------------------------------------------------------
// Setup 1: x NCHW fp32 -> NHWC fp16  [b][h][w][128 ic]
// ---------------------------------------------------------------------------
__global__ __launch_bounds__(256)
void xprep(const float* __restrict__ x) {
    __shared__ float tile[128][33];
    int wt = blockIdx.x, hh = blockIdx.y, b = blockIdx.z;
    int t = threadIdx.x, warp = t >> 5, lane = t & 31;
    const float* src = x + (((size_t)b * Cn + warp * 16) * Hn + hh) * Wn + wt * 32 + lane;
    #pragma unroll
    for (int k = 0; k < 16; k++) tile[warp * 16 + k][lane] = src[(size_t)k * Hn * Wn];
    __syncthreads();
    int px = t >> 3, seg = t & 7, icb = seg * 16;
    unsigned int hiv[8];
    #pragma unroll
    for (int j = 0; j < 16; j += 2) {
        __half h0 = __float2half_rn(tile[icb + j][px]);
        __half h1 = __float2half_rn(tile[icb + j + 1][px]);
        hiv[j >> 1] = (unsigned)h_bits(h0) | ((unsigned)h_bits(h1) << 16);
    }
    size_t p = ((size_t)b * Hn + hh) * Wn + wt * 32 + px;
    unsigned char* dst = g_xnhwc + p * 256;
    *(uint4*)(dst + icb * 2)      = make_uint4(hiv[0], hiv[1], hiv[2], hiv[3]);
    *(uint4*)(dst + icb * 2 + 16) = make_uint4(hiv[4], hiv[5], hiv[6], hiv[7]);
}

// ---------------------------------------------------------------------------
// Setup 2: weights -> g_w[tap][oc][ic] fp16
// ---------------------------------------------------------------------------
__global__ __launch_bounds__(256)
void wprep(const float* __restrict__ wa, const float* __restrict__ wb) {
    int id = blockIdx.x * 256 + threadIdx.x;
    if (id >= 9 * 128 * 128) return;
    int tap = id / 16384, rem = id & 16383, oc = rem >> 7, ic = rem & 127;
    float w = (oc < 64) ? wa[((size_t)oc * 128 + ic) * 9 + tap]
                        : wb[((size_t)(oc - 64) * 128 + ic) * 9 + tap];
    *(unsigned short*)(g_w + (((size_t)tap * 128 + oc) * 128 + ic) * 2) =
        h_bits(__float2half_rn(w));
}

// ---------------------------------------------------------------------------
// Pass 1: mma.sync fp16 implicit-GEMM conv, cp.async pipelined, 2 CTA/SM.
// CTA = 128 oc x 128 px. 8 warps: 2(oc) x 4(px). 1 MMA per k16.
// smem: W double buffer (2 x 32KB), X single buffer (33.3KB).
// ---------------------------------------------------------------------------
constexpr int SM_W    = 0;           // buf s at SM_W + s*32768
constexpr int SM_XH   = 65536;       // 130 x 256B = 33280
constexpr int SM_LUT  = 98816;       // 3 x 128 f32 = 1536
constexpr int SM_ATT  = 100352;      // 2 x 128 f32 = 1024
constexpr int SMEM_BYTES = 101376;   // 99 KB -> 2 CTAs/SM

__device__ __forceinline__ void stage_X(uint32_t sb32, const unsigned char* xbase,
                                        int ih, int px0, int tid) {
    const bool rowok = (unsigned)ih < (unsigned)Hn;
    const unsigned char* xrow = xbase + (size_t)(ih & 255) * (Wn * 256);
    for (int idx = tid; idx < 130 * 16; idx += 256) {
        int r = idx >> 4, c = idx & 15;
        int g = px0 - 1 + r;
        bool ok = rowok && ((unsigned)g < (unsigned)Wn);
        const unsigned char* src = xrow + (size_t)(g & 255) * 256 + c * 16;
        uint32_t off = (uint32_t)(r * 256 + ((c ^ (r & 7)) << 4));
        cp16(sb32 + SM_XH + off, src, ok);
    }
}
__device__ __forceinline__ void stage_W(uint32_t sb32, int tap, int bufsel, int tid) {
    const unsigned char* wsrc = g_w + (size_t)tap * 32768;
    uint32_t wb = sb32 + SM_W + bufsel * 32768;
    for (int idx = tid; idx < 128 * 16; idx += 256) {
        int r = idx >> 4, c = idx & 15;
        uint32_t off = (uint32_t)(r * 256 + ((c ^ (r & 7)) << 4));
        cp16(wb + off, wsrc + r * 256 + c * 16, true);
    }
}

__global__ __launch_bounds__(256, 2)
void pass1_mma(
    const float* __restrict__ ba, const float* __restrict__ bb,
    const float* __restrict__ bnag, const float* __restrict__ bnabt,
    const float* __restrict__ bnam, const float* __restrict__ bnav,
    const float* __restrict__ bnbg, const float* __restrict__ bnbbt,
    const float* __restrict__ bnbm, const float* __restrict__ bnbv,
    const float* __restrict__ attaw, const float* __restrict__ attab,
    const float* __restrict__ attbw, const float* __restrict__ attbbias,
    const float* __restrict__ abnag, const float* __restrict__ abnabt,
    const float* __restrict__ abnam, const float* __restrict__ abnav,
    const float* __restrict__ abnbg, const float* __restrict__ abnbbt,
    const float* __restrict__ abnbm, const float* __restrict__ abnbv,
    float* __restrict__ out)
{
    extern __shared__ char sb[];
    const uint32_t sb32 = smem_u32(sb);

    const int tid = threadIdx.x, wid = tid >> 5, lane = tid & 31;
    const int warpM = wid & 1, warpN = wid >> 1;
    const int px0 = (blockIdx.x & 1) * 128;
    const int h = blockIdx.y, b = blockIdx.z;
    const int ocb = warpM * 64, pxb = warpN * 32;
    const unsigned char* xbase = g_xnhwc + (size_t)b * Hn * (Wn * 256);

    // per-oc BN/attention LUTs
    if (tid < 128) {
        int oc = tid; bool isB = oc >= 64; int ol = oc & 63;
        float g  = isB ? bnbg[ol]  : bnag[ol];
        float bt = isB ? bnbbt[ol] : bnabt[ol];
        float mu = isB ? bnbm[ol]  : bnam[ol];
        float vr = isB ? bnbv[ol]  : bnav[ol];
        float cb = isB ? bb[ol]    : ba[ol];
        float sc = g * rsqrtf(vr + 1e-3f);
        float* lut = (float*)(sb + SM_LUT);
        lut[oc]       = sc;
        lut[128 + oc] = (cb - mu) * sc + bt;
        lut[256 + oc] = isB ? attbw[ol] : attaw[ol];
    }

    float acc[4][4][4];
    #pragma unroll
    for (int i = 0; i < 4; i++)
        #pragma unroll
        for (int j = 0; j < 4; j++)
            #pragma unroll
            for (int k = 0; k < 4; k++) acc[i][j][k] = 0.f;

    // -------- pipeline prologue --------
    stage_X(sb32, xbase, h - 1, px0, tid);   // kh = 0
    stage_W(sb32, 0, 0, tid);
    cp_commit();                              // {X(kh0), W0}
    stage_W(sb32, 1, 1, tid);
    cp_commit();                              // {W1}

    // -------- 9-tap mainloop --------
    #pragma unroll 1
    for (int t = 0; t < 9; t++) {
        if (t == 8) cp_wait<0>(); else cp_wait<1>();
        __syncthreads();

        const int kw = t - (t / 3) * 3;
        const uint32_t wbase = sb32 + SM_W + (uint32_t)(t & 1) * 32768;

        #pragma unroll 2
        for (int kc = 0; kc < 8; kc++) {
            const int cA = kc * 2;
            uint32_t ah[4][4];
            #pragma unroll
            for (int mt = 0; mt < 4; mt++) {
                int mrow = ocb + mt * 16 + (lane & 15);
                int cc = cA + (lane >> 4);
                uint32_t off = (uint32_t)(mrow * 256 + ((cc ^ (mrow & 7)) << 4));
                ldsm_x4(ah[mt], wbase + off);
            }
            uint32_t bh[2][4];
            #pragma unroll
            for (int ntp = 0; ntp < 2; ntp++) {
                int prow = pxb + ntp * 16 + (lane & 7) + ((lane & 16) ? 8 : 0) + kw;
                int cc = cA + ((lane >> 3) & 1);
                uint32_t off = (uint32_t)(prow * 256 + ((cc ^ (prow & 7)) << 4));
                ldsm_x4(bh[ntp], sb32 + SM_XH + off);
            }
            #pragma unroll
            for (int mt = 0; mt < 4; mt++)
                #pragma unroll
                for (int nt = 0; nt < 4; nt++)
                    mma16816h(acc[mt][nt], ah[mt], &bh[nt >> 1][(nt & 1) * 2]);
        }
        __syncthreads();   // compute done before buffers are overwritten

        if (t < 8) {
            if (((t + 1) % 3) == 0) {            // next tap starts a new kh
                stage_X(sb32, xbase, h + (t + 1) / 3 - 1, px0, tid);
                cp_commit();
            }
            if (t + 2 <= 8) {
                stage_W(sb32, t + 2, t & 1, tid);
                cp_commit();
            }
        }
    }

    // ---- epilogue: BN + store f + 1x1 attention partial ----
    const float* scl = (const float*)(sb + SM_LUT);
    const float* shl = scl + 128;
    const float* awl = scl + 256;
    float* attbuf = (float*)(sb + SM_ATT);

    #pragma unroll
    for (int nt = 0; nt < 4; nt++) {
        float s0 = 0.f, s1 = 0.f;
        const int pxl = pxb + nt * 8 + (lane & 3) * 2;
        #pragma unroll
        for (int mt = 0; mt < 4; mt++) {
            int oc0 = ocb + mt * 16 + (lane >> 2);
            int oc1 = oc0 + 8;
            float f0 = acc[mt][nt][0] * scl[oc0] + shl[oc0];
            float f1 = acc[mt][nt][1] * scl[oc0] + shl[oc0];
            float f2 = acc[mt][nt][2] * scl[oc1] + shl[oc1];
            float f3 = acc[mt][nt][3] * scl[oc1] + shl[oc1];
            s0 += awl[oc0] * f0 + awl[oc1] * f2;
            s1 += awl[oc0] * f1 + awl[oc1] * f3;
            float* o0 = out + (((size_t)b * Cn + oc0) << 16) + h * 256 + px0 + pxl;
            float* o1 = out + (((size_t)b * Cn + oc1) << 16) + h * 256 + px0 + pxl;
            *(float2*)o0 = make_float2(f0, f1);
            *(float2*)o1 = make_float2(f2, f3);
        }
        s0 += __shfl_xor_sync(0xffffffffu, s0, 4);
        s0 += __shfl_xor_sync(0xffffffffu, s0, 8);
        s0 += __shfl_xor_sync(0xffffffffu, s0, 16);
        s1 += __shfl_xor_sync(0xffffffffu, s1, 4);
        s1 += __shfl_xor_sync(0xffffffffu, s1, 8);
        s1 += __shfl_xor_sync(0xffffffffu, s1, 16);
        if (lane < 4) {
            attbuf[warpM * 128 + pxb + nt * 8 + lane * 2]     = s0;
            attbuf[warpM * 128 + pxb + nt * 8 + lane * 2 + 1] = s1;
        }
    }
    __syncthreads();

    if (tid < 128) {
        int px = px0 + tid;
        float pa = attbuf[tid];
        float pb = attbuf[128 + tid];
        float ghv = fabsf((float)h - 128.f + 0.5f) * (1.f / 128.f);
        float gwv = fabsf((float)px - 128.f + 0.5f) * (1.f / 128.f);
        float raA = pa + attab[0]    + attaw[64] * ghv + attaw[65] * gwv;
        float raB = pb + attbbias[0] + attbw[64] * ghv + attbw[65] * gwv;
        float aa = (raA - abnam[0]) * (abnag[0] * rsqrtf(abnav[0] + 1e-5f)) + abnabt[0];
        float ab = (raB - abnbm[0]) * (abnbg[0] * rsqrtf(abnbv[0] + 1e-5f)) + abnbbt[0];
        size_t pi = ((size_t)b * Hn + h) * Wn + px;
        g_att[0][pi] = aa;
        g_att[1][pi] = ab;
    }
}

// ---------------------------------------------------------------------------
// Pass 2: 3x3 attention conv + sigmoid, scale out.
// grid (256, 4): blockIdx.y selects a 32-channel chunk.
// ---------------------------------------------------------------------------
__global__ __launch_bounds__(256)
void pass2_attn_scale(
    const float* __restrict__ wA, const float* __restrict__ wB,
    const float* __restrict__ s1p, const float* __restrict__ s2p,
    float* __restrict__ out)
{
    int t = blockIdx.x * 256 + threadIdx.x;
    int b = t >> 14, rem = t & 16383, h = rem >> 6, w4 = (rem & 63) << 2;
    const int cch = blockIdx.y;           // 0..3 -> channels [cch*32, cch*32+32)
    const bool branchA = (cch < 2);

    const float ghmax = 127.5f / 128.f, ghmin = 0.5f / 128.f;
    float prmax = sqrtf(ghmax * ghmax + ghmax * ghmax);
    float prmin = sqrtf(ghmin * ghmin + ghmin * ghmin);
    float kk = 2.f / (prmax - prmin);
    float c0 = 1.f - prmax * kk;

    const float* att = g_att[branchA ? 0 : 1] + (size_t)b * Hn * Wn;
    const float* wgt = branchA ? wA : wB;
    float scale = branchA ? s1p[0] : s2p[0];

    float s[4] = {0.f, 0.f, 0.f, 0.f};
    #pragma unroll
    for (int kh = 0; kh < 3; kh++) {
        int ih = h + kh - 1;
        if ((unsigned)ih >= (unsigned)Hn) continue;
        float ghv = fabsf((float)ih - 128.f + 0.5f) * (1.f / 128.f);
        #pragma unroll
        for (int kw = 0; kw < 3; kw++) {
            int ti = kh * 3 + kw;
            float w0 = wgt[ti], w1 = wgt[9 + ti], w2 = wgt[18 + ti], w3 = wgt[27 + ti];
            #pragma unroll
            for (int i = 0; i < 4; i++) {
                int jw = w4 + i + kw - 1;
                if ((unsigned)jw >= (unsigned)Wn) continue;
                float gwv = fabsf((float)jw - 128.f + 0.5f) * (1.f / 128.f);
                float pr = kk * sqrtf(ghv * ghv + gwv * gwv) + c0;
                float av = att[(size_t)ih * Wn + jw];
                s[i] += w0 * av + w1 * ghv + w2 * gwv + w3 * pr;
            }
        }
    }
    float m[4];
    #pragma unroll
    for (int i = 0; i < 4; i++) m[i] = scale / (1.f + expf(-s[i]));

    float* base = out + (((size_t)b * Cn + cch * 32) * Hn + h) * Wn + w4;
    #pragma unroll 4
    for (int c = 0; c < 32; c++) {
        float4* p = (float4*)(base + (size_t)c * Hn * Wn);
        float4 v = *p;
        v.x *= m[0]; v.y *= m[1]; v.z *= m[2]; v.w *= m[3];
        *p = v;
    }
}

extern "C" void kernel_launch(void* const* d_in, const int* in_sizes, int n_in,
                              void* d_out, int out_size) {
    (void)in_sizes; (void)n_in; (void)out_size;
    const float* P[29];
    for (int i = 0; i < 29; i++) P[i] = (const float*)d_in[i];
    float* out = (float*)d_out;

    cudaFuncSetAttribute(pass1_mma, cudaFuncAttributeMaxDynamicSharedMemorySize, SMEM_BYTES);

    dim3 gx(8, 256, 4);
    xprep<<<gx, 256>>>(P[0]);
    wprep<<<(9 * 128 * 128 + 255) / 256, 256>>>(P[1], P[3]);
    dim3 g1(2, 256, 4);
    pass1_mma<<<g1, 256, SMEM_BYTES>>>(
        P[2], P[4],                   // conv biases a, b
        P[5], P[6], P[7], P[8],       // bn a
        P[9], P[10], P[11], P[12],    // bn b
        P[13], P[14], P[15], P[16],   // att 1x1 w/b a, b
        P[17], P[18], P[19], P[20],   // att bn a
        P[21], P[22], P[23], P[24],   // att bn b
        out);
    dim3 g2((Bn * Hn * Wn / 4) / 256, 4);
    pass2_attn_scale<<<g2, 256>>>(P[25], P[26], P[27], P[28], out);
}